// round 17
// baseline (speedup 1.0000x reference)
#include <cuda_runtime.h>
#include <cuda_fp16.h>
#include <cstdint>

#define D_DIM 768
#define H_DIM 3072
#define E_NUM 8
#define MAX_T 4096
#define RT_TOK 8
#define W2CVT 128           // W2 convert chunks in the work queue
#define NW4 (E_NUM * D_DIM * H_DIM / 8)      // uint4 count of W (2359296)
#define W2CHUNK (NW4 / W2CVT)                // 18432 uint4 per chunk

// ---------------- device scratch ----------------
__device__ int    g_counts[E_NUM];
__device__ int    g_done;
__device__ int    g_ntiles;
__device__ int    g_tmap[256];
__device__ int    g_work;
__device__ int    g_w2done;
__device__ int    g_tdone[256];
__device__ int    g_tok [E_NUM * MAX_T];
__device__ int    g_slot[E_NUM * MAX_T];
__device__ float  g_pslot[2 * MAX_T];
__device__ __half g_xh [(size_t)MAX_T * D_DIM];
__device__ __half g_hid[(size_t)2 * MAX_T * H_DIM];
__device__ float  g_y  [(size_t)2 * MAX_T * D_DIM];   // p-scaled expert outputs
__device__ __half g_w1h[(size_t)E_NUM * D_DIM * H_DIM];
__device__ __half g_w2h[(size_t)E_NUM * H_DIM * D_DIM];

// ---------------- PTX helpers ----------------
__device__ __forceinline__ uint32_t smem_u32(const void* p) {
    uint32_t r;
    asm("{ .reg .u64 t; cvta.to.shared.u64 t, %1; cvt.u32.u64 %0, t; }"
        : "=r"(r) : "l"(p));
    return r;
}
__device__ __forceinline__ void mma_f16(float* d, const uint4& a, const uint2& b) {
    asm volatile(
        "mma.sync.aligned.m16n8k16.row.col.f32.f16.f16.f32 "
        "{%0,%1,%2,%3}, {%4,%5,%6,%7}, {%8,%9}, {%0,%1,%2,%3};"
        : "+f"(d[0]), "+f"(d[1]), "+f"(d[2]), "+f"(d[3])
        : "r"(a.x), "r"(a.y), "r"(a.z), "r"(a.w), "r"(b.x), "r"(b.y));
}
__device__ __forceinline__ void ldsm_x4(uint4& r, uint32_t addr) {
    asm volatile("ldmatrix.sync.aligned.m8n8.x4.shared.b16 {%0,%1,%2,%3}, [%4];"
                 : "=r"(r.x), "=r"(r.y), "=r"(r.z), "=r"(r.w) : "r"(addr));
}
__device__ __forceinline__ void ldsm_x4t(uint4& r, uint32_t addr) {
    asm volatile("ldmatrix.sync.aligned.m8n8.x4.trans.shared.b16 {%0,%1,%2,%3}, [%4];"
                 : "=r"(r.x), "=r"(r.y), "=r"(r.z), "=r"(r.w) : "r"(addr));
}
__device__ __forceinline__ void cp16(uint32_t dst, const void* src, uint32_t sz) {
    asm volatile("cp.async.cg.shared.global [%0], [%1], 16, %2;"
                 :: "r"(dst), "l"(src), "r"(sz) : "memory");
}
__device__ __forceinline__ void cp_commit() {
    asm volatile("cp.async.commit_group;" ::: "memory");
}
__device__ __forceinline__ void cp_wait1() {
    asm volatile("cp.async.wait_group 1;" ::: "memory");
}
__device__ __forceinline__ void cp_wait0() {
    asm volatile("cp.async.wait_group 0;" ::: "memory");
}

// ---------------- fp32 -> fp16 convert (W1 prologue) ----------------
__global__ void __launch_bounds__(256) convert_f2h(
    const float* __restrict__ src, __half* __restrict__ dst, int n8)
{
    int i = blockIdx.x * 256 + threadIdx.x;
    if (i >= n8) return;
    const float4* s = (const float4*)src + 2 * (size_t)i;
    float4 a = s[0], b = s[1];
    __half2 h0 = __floats2half2_rn(a.x, a.y);
    __half2 h1 = __floats2half2_rn(a.z, a.w);
    __half2 h2 = __floats2half2_rn(b.x, b.y);
    __half2 h3 = __floats2half2_rn(b.z, b.w);
    uint4 o;
    o.x = *(uint32_t*)&h0; o.y = *(uint32_t*)&h1;
    o.z = *(uint32_t*)&h2; o.w = *(uint32_t*)&h3;
    ((uint4*)dst)[i] = o;
}

// ---------------- routing ----------------
__global__ void zero_counts_kernel() {
    int tid = threadIdx.x;
    if (tid < E_NUM) g_counts[tid] = 0;
    if (tid == 0) { g_done = 0; g_work = 0; g_w2done = 0; }
    if (tid < 256) g_tdone[tid] = 0;
}

__global__ void __launch_bounds__(256) route_kernel(
    const float* __restrict__ x, const float* __restrict__ noise,
    const float* __restrict__ Wg, const float* __restrict__ bg,
    const float* __restrict__ Wn, const float* __restrict__ bn, int T)
{
    __shared__ float sW[D_DIM * 18];
    __shared__ int sE[16], sT2[16];
    __shared__ int sBase[E_NUM];
    __shared__ int s_last;

    int tid = threadIdx.x, wid = tid >> 5, lane = tid & 31;

    if (tid < 16) sE[tid] = -1;
    for (int idx = tid; idx < D_DIM * E_NUM; idx += 256) {
        int d = idx >> 3, e = idx & 7;
        sW[d * 18 + 2 * e]     = Wg[idx];
        sW[d * 18 + 2 * e + 1] = Wn[idx];
    }
    __syncthreads();

    int t = blockIdx.x * RT_TOK + wid;
    if (t < T) {
        float pg[E_NUM], pn[E_NUM];
#pragma unroll
        for (int e = 0; e < E_NUM; e++) { pg[e] = 0.f; pn[e] = 0.f; }

        const float* xr = x + (size_t)t * D_DIM;
        __half* xhr = g_xh + (size_t)t * D_DIM;
#pragma unroll
        for (int i = 0; i < D_DIM / 32; i++) {
            int d = lane + 32 * i;
            float xv = xr[d];
            xhr[d] = __float2half_rn(xv);
            const float2* w = (const float2*)(sW + d * 18);
#pragma unroll
            for (int e = 0; e < E_NUM; e++) {
                float2 wv = w[e];
                pg[e] = fmaf(xv, wv.x, pg[e]);
                pn[e] = fmaf(xv, wv.y, pn[e]);
            }
        }
#pragma unroll
        for (int e = 0; e < E_NUM; e++)
#pragma unroll
            for (int o = 16; o > 0; o >>= 1) {
                pg[e] += __shfl_down_sync(0xffffffffu, pg[e], o);
                pn[e] += __shfl_down_sync(0xffffffffu, pn[e], o);
            }

        if (lane == 0) {
            float h[E_NUM];
#pragma unroll
            for (int e = 0; e < E_NUM; e++) {
                float a = pg[e] + bg[e];
                float b = pn[e] + bn[e];
                float sp = fmaxf(b, 0.f) + log1pf(expf(-fabsf(b)));
                h[e] = a + noise[(size_t)t * E_NUM + e] * sp;
            }
            int i0 = 0;
#pragma unroll
            for (int e = 1; e < E_NUM; e++) if (h[e] > h[i0]) i0 = e;
            int i1 = (i0 == 0) ? 1 : 0;
#pragma unroll
            for (int e = 0; e < E_NUM; e++) if (e != i0 && h[e] > h[i1]) i1 = e;

            float p0 = 1.f / (1.f + expf(h[i1] - h[i0]));
            g_pslot[2 * t]     = p0;
            g_pslot[2 * t + 1] = 1.f - p0;
            sE[2 * wid]     = i0;  sT2[2 * wid]     = t;
            sE[2 * wid + 1] = i1;  sT2[2 * wid + 1] = t;
        }
    }
    __syncthreads();

    if (tid < E_NUM) {
        int c = 0;
#pragma unroll
        for (int j = 0; j < 16; j++) c += (sE[j] == tid);
        sBase[tid] = c ? atomicAdd(&g_counts[tid], c) : 0;
    }
    __syncthreads();
    if (tid < 16 && sE[tid] >= 0) {
        int e = sE[tid], r = 0;
#pragma unroll
        for (int j = 0; j < 16; j++) r += (j < tid && sE[j] == e);
        int pos = sBase[e] + r;
        g_tok [e * MAX_T + pos] = sT2[tid];
        g_slot[e * MAX_T + pos] = 2 * sT2[tid] + (tid & 1);
    }

    __threadfence();
    __syncthreads();
    if (tid == 0) {
        int prev = atomicAdd(&g_done, 1);
        s_last = (prev == (int)gridDim.x - 1) ? 1 : 0;
    }
    __syncthreads();
    if (s_last && tid == 0) {
        __threadfence();
        int c = 0;
#pragma unroll
        for (int e = 0; e < E_NUM; e++) {
            int nt = (g_counts[e] + 127) >> 7;
            for (int m = 0; m < nt; m++) g_tmap[c++] = (e << 16) | m;
        }
        g_ntiles = c;
        __threadfence();
    }
}

// ---------------- GEMM tile body (shared by persistent scheduler) ----------
#define STAGE_BYTES 32768
#define SM_BYTES (3 * STAGE_BYTES)

template <bool G1>
__device__ __forceinline__ void gemm_tile(
    int e, int m0, int n0, int cnt,
    const __half* __restrict__ Ah, const __half* __restrict__ Wh,
    const float* __restrict__ bias, void* __restrict__ OutV, char* smem)
{
    constexpr int KTOT = G1 ? D_DIM : H_DIM;
    constexpr int NG   = G1 ? H_DIM : D_DIM;
    constexpr int NC   = KTOT / 64;

    uint32_t sbase = smem_u32(smem);
    int tid = threadIdx.x, wid = tid >> 5, lane = tid & 31;
    int wm = wid >> 2, wn = wid & 3;
    const int* idxarr = G1 ? g_tok : g_slot;

    int ar0 = tid >> 3, akq = tid & 7;
    uint32_t a_dst0 = (uint32_t)(ar0 * 8 + (akq ^ (ar0 & 7))) * 16;
    const __half* a_src[4]; uint32_t a_sz[4];
#pragma unroll
    for (int i = 0; i < 4; i++) {
        int gr = m0 + ar0 + 32 * i;
        if (gr < cnt) {
            a_src[i] = Ah + (size_t)idxarr[e * MAX_T + gr] * KTOT + akq * 8;
            a_sz[i] = 16;
        } else { a_src[i] = Ah; a_sz[i] = 0; }
    }
    int bk0 = tid >> 4, bnq = tid & 15;
    const __half* b_src = Wh + (size_t)e * KTOT * NG + (size_t)bk0 * NG
                        + n0 + bnq * 8;
    uint32_t b_dst0 = 16384u + (uint32_t)(bk0 * 16 + (bnq ^ (bk0 & 7))) * 16;

    auto issue = [&](int c) {
        if (c < NC) {
            uint32_t sa = sbase + (uint32_t)(c % 3) * STAGE_BYTES;
#pragma unroll
            for (int i = 0; i < 4; i++)
                cp16(sa + a_dst0 + (uint32_t)i * 4096,
                     a_src[i] + (size_t)c * 64, a_sz[i]);
            const __half* bs = b_src + (size_t)c * 64 * NG;
#pragma unroll
            for (int j = 0; j < 4; j++)
                cp16(sa + b_dst0 + (uint32_t)j * 4096,
                     bs + (size_t)(16 * j) * NG, 16);
        }
        cp_commit();
    };

    issue(0); issue(1);

    int lrow = (lane & 7) + 8 * ((lane >> 3) & 1);
    int lsel = lane >> 4;

    float acc[4][4][4];
#pragma unroll
    for (int a = 0; a < 4; a++)
#pragma unroll
        for (int b = 0; b < 4; b++)
#pragma unroll
            for (int k = 0; k < 4; k++) acc[a][b][k] = 0.f;

#pragma unroll 1
    for (int c = 0; c < NC; c++) {
        cp_wait1();
        __syncthreads();
        issue(c + 2);

        uint32_t sa = sbase + (uint32_t)(c % 3) * STAGE_BYTES;
        uint32_t sb = sa + 16384u;
#pragma unroll
        for (int ks = 0; ks < 4; ks++) {
            uint4 af[4]; uint2 bf[4];
            int kq = ks * 2 + lsel;
#pragma unroll
            for (int mf = 0; mf < 4; mf++) {
                int row = wm * 64 + mf * 16 + lrow;
                ldsm_x4(af[mf], sa + (uint32_t)(row * 8 + (kq ^ (row & 7))) * 16);
            }
            int kb = ks * 16 + lrow;
#pragma unroll
            for (int np = 0; np < 2; np++) {
                int gnfp = wn * 2 + np;
                int nq = gnfp * 2 + lsel;
                uint4 bb;
                ldsm_x4t(bb, sb + (uint32_t)(kb * 16 + (nq ^ (kb & 7))) * 16);
                bf[2 * np].x     = bb.x; bf[2 * np].y     = bb.y;
                bf[2 * np + 1].x = bb.z; bf[2 * np + 1].y = bb.w;
            }
#pragma unroll
            for (int mf = 0; mf < 4; mf++)
#pragma unroll
                for (int nf = 0; nf < 4; nf++)
                    mma_f16(acc[mf][nf], af[mf], bf[nf]);
        }
    }
    cp_wait0();   // drain tail empty groups before tile retires

#pragma unroll
    for (int mf = 0; mf < 4; mf++) {
        int r0 = m0 + wm * 64 + mf * 16 + (lane >> 2);
        int r1 = r0 + 8;
        bool v0 = r0 < cnt, v1 = r1 < cnt;
        int s0 = v0 ? g_slot[e * MAX_T + r0] : 0;
        int s1 = v1 ? g_slot[e * MAX_T + r1] : 0;
        float p0 = 1.f, p1 = 1.f;
        if (!G1) {
            p0 = v0 ? g_pslot[s0] : 0.f;
            p1 = v1 ? g_pslot[s1] : 0.f;
        }
#pragma unroll
        for (int nf = 0; nf < 4; nf++) {
            int col = n0 + wn * 32 + nf * 8 + (lane & 3) * 2;
            float2 bb = *(const float2*)&bias[(size_t)e * NG + col];
            float x0 = acc[mf][nf][0] + bb.x, x1 = acc[mf][nf][1] + bb.y;
            float x2 = acc[mf][nf][2] + bb.x, x3 = acc[mf][nf][3] + bb.y;
            if (G1) {
                x0 = fmaxf(x0, 0.f); x1 = fmaxf(x1, 0.f);
                x2 = fmaxf(x2, 0.f); x3 = fmaxf(x3, 0.f);
                __half* Out = (__half*)OutV;
                if (v0) {
                    __half2 hv = __floats2half2_rn(x0, x1);
                    *(__half2*)(Out + (size_t)s0 * NG + col) = hv;
                }
                if (v1) {
                    __half2 hv = __floats2half2_rn(x2, x3);
                    *(__half2*)(Out + (size_t)s1 * NG + col) = hv;
                }
            } else {
                float* Out = (float*)OutV;
                if (v0) { float2 o; o.x = p0 * x0; o.y = p0 * x1;
                          *(float2*)(Out + (size_t)s0 * NG + col) = o; }
                if (v1) { float2 o; o.x = p1 * x2; o.y = p1 * x3;
                          *(float2*)(Out + (size_t)s1 * NG + col) = o; }
            }
        }
    }
}

// ---------------- persistent scheduler ----------------
// Queue: [0, W2CVT)                : W2 fp32->fp16 convert chunks
//        [W2CVT, W2CVT+nt*24)      : GEMM1 tiles (n fastest)
//        [.., +nt*6)               : GEMM2 tiles (gated on g_tdone / g_w2done)
__global__ void __launch_bounds__(256, 2) moe_persist(
    const float* __restrict__ W2f,
    const float* __restrict__ b1, const float* __restrict__ b2)
{
    extern __shared__ char smem[];
    __shared__ int s_idx;
    int tid = threadIdx.x;

    for (;;) {
        if (tid == 0) s_idx = atomicAdd(&g_work, 1);
        __syncthreads();
        int idx = s_idx;
        int nt = g_ntiles;

        if (idx < W2CVT) {
            // convert W2 chunk
            size_t base = (size_t)idx * W2CHUNK;
            const float4* src = (const float4*)W2f;
            uint4* dst = (uint4*)g_w2h;
#pragma unroll 4
            for (int j = tid; j < W2CHUNK; j += 256) {
                size_t i = base + j;
                float4 a = src[2 * i], b = src[2 * i + 1];
                __half2 h0 = __floats2half2_rn(a.x, a.y);
                __half2 h1 = __floats2half2_rn(a.z, a.w);
                __half2 h2 = __floats2half2_rn(b.x, b.y);
                __half2 h3 = __floats2half2_rn(b.z, b.w);
                uint4 o;
                o.x = *(uint32_t*)&h0; o.y = *(uint32_t*)&h1;
                o.z = *(uint32_t*)&h2; o.w = *(uint32_t*)&h3;
                dst[i] = o;
            }
            __threadfence();
            __syncthreads();
            if (tid == 0) atomicAdd(&g_w2done, 1);
        } else if (idx - W2CVT < nt * 24) {
            int i1 = idx - W2CVT;
            int ym = i1 / 24, nx = i1 % 24;
            int tm = g_tmap[ym];
            int e = tm >> 16, m0 = (tm & 0xFFFF) * 128;
            gemm_tile<true>(e, m0, nx * 128, g_counts[e],
                            g_xh, g_w1h, b1, g_hid, smem);
            __threadfence();
            __syncthreads();
            if (tid == 0) atomicAdd(&g_tdone[ym], 1);
        } else if (idx - W2CVT - nt * 24 < nt * 6) {
            int i2 = idx - W2CVT - nt * 24;
            int ym = i2 / 6, nx = i2 % 6;
            if (tid == 0) {
                while (atomicAdd(&g_w2done, 0) < W2CVT) __nanosleep(128);
                while (atomicAdd(&g_tdone[ym], 0) < 24) __nanosleep(128);
            }
            __syncthreads();
            int tm = g_tmap[ym];
            int e = tm >> 16, m0 = (tm & 0xFFFF) * 128;
            gemm_tile<false>(e, m0, nx * 128, g_counts[e],
                             g_hid, g_w2h, b2, g_y, smem);
        } else {
            break;
        }
        __syncthreads();   // protect s_idx before next pop
    }
}

// out[t] = y[2t] + y[2t+1]   (y already gate-scaled)
__global__ void __launch_bounds__(256) combine_kernel(float* __restrict__ out, int T)
{
    int idx = blockIdx.x * 256 + threadIdx.x;
    int total = T * (D_DIM / 4);
    if (idx >= total) return;
    int t  = idx / (D_DIM / 4);
    int c4 = idx % (D_DIM / 4);
    float4 a = ((const float4*)(g_y + (size_t)(2 * t) * D_DIM))[c4];
    float4 b = ((const float4*)(g_y + (size_t)(2 * t + 1) * D_DIM))[c4];
    float4 o;
    o.x = a.x + b.x;
    o.y = a.y + b.y;
    o.z = a.z + b.z;
    o.w = a.w + b.w;
    ((float4*)out)[idx] = o;
}

extern "C" void kernel_launch(void* const* d_in, const int* in_sizes, int n_in,
                              void* d_out, int out_size)
{
    const float* x     = (const float*)d_in[0];
    const float* noise = (const float*)d_in[1];
    const float* Wg    = (const float*)d_in[2];
    const float* bg    = (const float*)d_in[3];
    const float* Wn    = (const float*)d_in[4];
    const float* bn    = (const float*)d_in[5];
    const float* W1    = (const float*)d_in[6];
    const float* b1    = (const float*)d_in[7];
    const float* W2    = (const float*)d_in[8];
    const float* b2    = (const float*)d_in[9];
    float* out = (float*)d_out;

    int T = in_sizes[0] / D_DIM;
    if (T > MAX_T) T = MAX_T;

    static bool s_init = false;
    static cudaStream_t s1;
    static cudaEvent_t ev0, ev1;
    if (!s_init) {
        cudaStreamCreateWithFlags(&s1, cudaStreamNonBlocking);
        cudaEventCreateWithFlags(&ev0, cudaEventDisableTiming);
        cudaEventCreateWithFlags(&ev1, cudaEventDisableTiming);
        cudaFuncSetAttribute(moe_persist,
                             cudaFuncAttributeMaxDynamicSharedMemorySize, SM_BYTES);
        s_init = true;
    }

    __half *xh = nullptr, *w1h = nullptr;
    cudaGetSymbolAddress((void**)&xh,  g_xh);
    cudaGetSymbolAddress((void**)&w1h, g_w1h);

    int nw = E_NUM * D_DIM * H_DIM / 8;

    zero_counts_kernel<<<1, 256>>>();
    cudaEventRecord(ev0, 0);
    cudaStreamWaitEvent(s1, ev0, 0);
    convert_f2h<<<(nw + 255) / 256, 256, 0, s1>>>(W1, w1h, nw);
    cudaEventRecord(ev1, s1);

    route_kernel<<<(T + RT_TOK - 1) / RT_TOK, 256>>>(x, noise, Wg, bg, Wn, bn, T);

    cudaStreamWaitEvent(0, ev1, 0);   // join W1 convert
    moe_persist<<<296, 256, SM_BYTES>>>(W2, b1, b2);

    combine_kernel<<<(T * (D_DIM / 4) + 255) / 256, 256>>>(out, T);
}